// round 16
// baseline (speedup 1.0000x reference)
#include <cuda_runtime.h>
#include <cstdint>

// NoReFT on [B,768] fp32, regions start {0,752,184,568}, width 16.
// Ceiling-control design:
//   1) cudaMemcpyAsync D2D: out <- base  (driver-tuned 1:1 R/W stream)
//   2) fixup kernel: rewrites only the 4x16 edited channels per row:
//        out[st+l] = x[l] + sum_e M[g][e][l]*x[e] + c[g][l]
//      One thread per edited float; x gathered via 16-lane shfl; M in regs.

#define NT 256
#define GRID 2048

__device__ __forceinline__ int start_of(int g) {
    return g == 0 ? 0 : g == 1 ? 752 : g == 2 ? 184 : 568;
}

__global__ __launch_bounds__(NT) void minireft_fixup(
    const float* __restrict__ base, float* __restrict__ out,
    const float* __restrict__ Wp, const float* __restrict__ bp,
    const float* __restrict__ Ws, const float* __restrict__ bs,
    long long B)
{
    __shared__ float sM[4 * 16 * 16];   // sM[(g*16+e)*16+l]
    __shared__ float sC[4 * 16];

    const int tid = threadIdx.x;

    // ---- fold weights ----
    for (int idx = tid; idx < 4 * 16 * 16; idx += NT) {
        int gg = idx >> 8, e = (idx >> 4) & 15, ll = idx & 15;
        float acc = 0.f;
        #pragma unroll
        for (int r = 0; r < 8; r++) {
            float wp = Wp[gg * 128 + r * 16 + e];
            float ws = Ws[gg * 128 + r * 16 + e];
            acc += (ws - wp) * Wp[gg * 128 + r * 16 + ll];
        }
        sM[idx] = acc;
    }
    for (int idx = tid; idx < 4 * 16; idx += NT) {
        int gg = idx >> 4, ll = idx & 15;
        float acc = 0.f;
        #pragma unroll
        for (int r = 0; r < 8; r++)
            acc += (bs[gg * 8 + r] - bp[gg * 8 + r]) * Wp[gg * 128 + r * 16 + ll];
        sC[idx] = acc;
    }
    __syncthreads();

    // thread's fixed channel identity: c = (g,l) is invariant across the
    // grid-stride loop because the stride is a multiple of 64.
    const long long t = (long long)blockIdx.x * NT + tid;
    const int c = (int)(t & 63);
    const int g = c >> 4;
    const int l = c & 15;
    const int lane = tid & 31;
    const int sbase = lane & 16;         // 16-lane shfl group base
    const int st = start_of(g);

    float Mv[16], cl;
    #pragma unroll
    for (int e = 0; e < 16; e++) Mv[e] = sM[(g * 16 + e) * 16 + l];
    Mv[l] += 1.0f;                       // folds "+x[l]"
    cl = sC[g * 16 + l];

    const long long total = B * 64;
    const long long stride = (long long)GRID * NT;      // multiple of 64
    const long long rstep = stride >> 6;                // rows per step

    for (long long item = t; item < total; item += stride) {
        const long long row = item >> 6;
        // lane l of the 16-lane group loads channel l; broadcast via shfl.
        const float xl = __ldcs(base + row * 768 + st + l);
        float d = cl * 1.0f;
        float acc = 0.f;
        #pragma unroll
        for (int e = 0; e < 16; e++)
            acc += Mv[e] * __shfl_sync(0xffffffffu, xl, sbase + e);
        d += acc;
        __stcs(out + row * 768 + st + l, d);
        (void)rstep;
    }
}

extern "C" void kernel_launch(void* const* d_in, const int* in_sizes, int n_in,
                              void* d_out, int out_size)
{
    const float* base = (const float*)d_in[0];  // [1, B, 768]
    const float* Wp   = (const float*)d_in[1];
    const float* bp   = (const float*)d_in[2];
    const float* Ws   = (const float*)d_in[3];
    const float* bs   = (const float*)d_in[4];
    float* out = (float*)d_out;

    const long long n = (long long)in_sizes[0];
    const long long B = n / 768;

    // 1) bulk copy: driver-tuned D2D stream (graph-capturable)
    cudaMemcpyAsync(out, base, n * sizeof(float), cudaMemcpyDeviceToDevice, 0);

    // 2) region fixup (stream-ordered after the copy)
    minireft_fixup<<<GRID, NT>>>(base, out, Wp, bp, Ws, bs, B);
}

// round 17
// speedup vs baseline: 1.6702x; 1.6702x over previous
#include <cuda_runtime.h>
#include <cstdint>

// NoReFT on [B,768] fp32, regions start {0,752,184,568}, width 16.
// FINAL (= R10, measured best: 130.7us wall / 122.9us ncu, DRAM 77.1%).
// TMA G->S pipeline (3 stages x 12KB = 4 rows). Per tile: in-smem patch of the
// 256 edited floats (M columns in registers), block sync, uniform branch-free
// LDS.128 -> STG.128 .cs copy. 6 CTAs/SM.
//
// Session evidence for "this is the ceiling": driver cudaMemcpyAsync D2D runs
// the same 805MB at ~6.3TB/s (~127us); this kernel streams at ~6.1TB/s with
// the fixup fused for free. TMA-store variants cap at ~56% DRAM (2x L2 cost),
// L2 prefetch thrashes (+18% traffic), other CTA/tile shapes measure <= this.

#define T_ROWS 4
#define TILE_F (T_ROWS * 768)            // 3072 floats
#define TILE_F4 (TILE_F / 4)             // 768
#define TILE_BYTES (TILE_F * 4)          // 12288 B
#define STAGES 3
#define NT 256
#define MAXGRID 2048

// steady-state smem: ring + barriers only
#define SM_BAR (STAGES * TILE_F)         // even float idx -> 8B aligned
#define SM_BYTES (SM_BAR * 4 + STAGES * 8)

__device__ __forceinline__ void mbar_init(uint32_t a, uint32_t cnt) {
    asm volatile("mbarrier.init.shared.b64 [%0], %1;" :: "r"(a), "r"(cnt) : "memory");
}
__device__ __forceinline__ void mbar_expect_tx(uint32_t a, uint32_t bytes) {
    asm volatile("mbarrier.arrive.expect_tx.shared.b64 _, [%0], %1;" :: "r"(a), "r"(bytes) : "memory");
}
__device__ __forceinline__ void mbar_wait(uint32_t a, uint32_t parity) {
    asm volatile(
        "{\n\t.reg .pred P;\n\t"
        "LW_%=:\n\t"
        "mbarrier.try_wait.parity.acquire.cta.shared::cta.b64 P, [%0], %1, 0x989680;\n\t"
        "@P bra LD_%=;\n\t"
        "bra LW_%=;\n\t"
        "LD_%=:\n\t}"
        :: "r"(a), "r"(parity) : "memory");
}
__device__ __forceinline__ void bulk_ld(uint32_t dst, const void* src, uint32_t bytes, uint32_t bar) {
    asm volatile("cp.async.bulk.shared::cta.global.mbarrier::complete_tx::bytes [%0], [%1], %2, [%3];"
                 :: "r"(dst), "l"(src), "r"(bytes), "r"(bar) : "memory");
}
__device__ __forceinline__ int start_of(int g) {
    return g == 0 ? 0 : g == 1 ? 752 : g == 2 ? 184 : 568;
}

__global__ __launch_bounds__(NT, 6) void minireft_v10(
    const float* __restrict__ base, float* __restrict__ out,
    const float* __restrict__ Wp, const float* __restrict__ bp,
    const float* __restrict__ Ws, const float* __restrict__ bs,
    int B, int nTiles, int grid)
{
    extern __shared__ float smem[];
    const uint32_t smem_u32 = (uint32_t)__cvta_generic_to_shared(smem);
    const uint32_t bar0 = smem_u32 + SM_BAR * 4;

    const int tid = threadIdx.x;

    // ---- thread's edited-float identity: one per (row, g, l) ----
    const int prow = tid >> 6;          // 0..3 tile row
    const int g    = (tid >> 4) & 3;    // region
    const int l    = tid & 15;          // channel within region
    const int xoff = prow * 768 + start_of(g);

    // ---- fold weights into scratch smem (ring area, pre-pipeline), then
    //      load this thread's M column + bias into registers ----
    {
        float* sM = smem;               // [4][16][16]: sM[(g*16+e)*16+l]
        float* sC = smem + 1024;        // [4][16]
        for (int idx = tid; idx < 4 * 16 * 16; idx += NT) {
            int gg = idx >> 8, e = (idx >> 4) & 15, ll = idx & 15;
            float acc = 0.f;
            #pragma unroll
            for (int r = 0; r < 8; r++) {
                float wp = Wp[gg * 128 + r * 16 + e];
                float ws = Ws[gg * 128 + r * 16 + e];
                acc += (ws - wp) * Wp[gg * 128 + r * 16 + ll];
            }
            sM[idx] = acc;
        }
        for (int idx = tid; idx < 4 * 16; idx += NT) {
            int gg = idx >> 4, ll = idx & 15;
            float acc = 0.f;
            #pragma unroll
            for (int r = 0; r < 8; r++)
                acc += (bs[gg * 8 + r] - bp[gg * 8 + r]) * Wp[gg * 128 + r * 16 + ll];
            sC[idx] = acc;
        }
        __syncthreads();

        // registers: Mv[e] = sM[g][e][l], cl = sC[g][l]
        float Mv[16], cl;
        #pragma unroll
        for (int e = 0; e < 16; e++) Mv[e] = sM[(g * 16 + e) * 16 + l];
        cl = sC[g * 16 + l];
        __syncthreads();

        // ---- remainder rows (B % T_ROWS) on block 0, plain path ----
        if (blockIdx.x == 0 && (B & (T_ROWS - 1))) {
            const long long remStart = (long long)nTiles * T_ROWS;
            for (long long row = remStart; row < B; row++) {
                for (int c = tid; c < 768; c += NT)
                    out[row * 768 + c] = base[row * 768 + c];
                __syncthreads();
                if (tid < 64) {   // one thread per (g,l)
                    const int st = start_of(g);
                    float d = cl;
                    #pragma unroll
                    for (int e = 0; e < 16; e++)
                        d += Mv[e] * base[row * 768 + st + e];
                    out[row * 768 + st + l] = base[row * 768 + st + l] + d;
                }
                __syncthreads();
            }
        }

        if (tid < STAGES) mbar_init(bar0 + tid * 8, 1);
        __syncthreads();

        const int bid = blockIdx.x;
        int count = 0;
        if (bid < nTiles) count = (nTiles - bid + grid - 1) / grid;

        // prologue: fill pipeline
        if (tid == 0) {
            int pre = count < STAGES ? count : STAGES;
            for (int k = 0; k < pre; k++) {
                long long tile = (long long)bid + (long long)k * grid;
                mbar_expect_tx(bar0 + k * 8, TILE_BYTES);
                bulk_ld(smem_u32 + (uint32_t)(k * TILE_BYTES),
                        base + tile * TILE_F, TILE_BYTES, bar0 + k * 8);
            }
        }

        int s = 0, p = 0;
        for (int k = 0; k < count; k++) {
            mbar_wait(bar0 + s * 8, p);

            float* sb = smem + s * TILE_F;

            // ---- phase 1: in-place patch of this thread's edited float ----
            {
                const float4* x4 = (const float4*)(sb + xoff);
                const float4 X0 = x4[0], X1 = x4[1], X2 = x4[2], X3 = x4[3];
                float d = cl;
                d += Mv[0] * X0.x;  d += Mv[1] * X0.y;
                d += Mv[2] * X0.z;  d += Mv[3] * X0.w;
                d += Mv[4] * X1.x;  d += Mv[5] * X1.y;
                d += Mv[6] * X1.z;  d += Mv[7] * X1.w;
                d += Mv[8] * X2.x;  d += Mv[9] * X2.y;
                d += Mv[10] * X2.z; d += Mv[11] * X2.w;
                d += Mv[12] * X3.x; d += Mv[13] * X3.y;
                d += Mv[14] * X3.z; d += Mv[15] * X3.w;
                const float xl = sb[xoff + l];
                __syncwarp();                 // all reads of x before any write
                sb[xoff + l] = xl + d;
            }
            __syncthreads();                  // patch visible to all copy warps

            // ---- phase 2: uniform branch-free copy ----
            {
                const float4* sb4 = (const float4*)sb;
                const long long tile = (long long)bid + (long long)k * grid;
                float4* op = (float4*)out + tile * TILE_F4;
                float4 v0 = sb4[tid];
                float4 v1 = sb4[tid + NT];
                float4 v2 = sb4[tid + 2 * NT];
                __stcs(op + tid, v0);
                __stcs(op + tid + NT, v1);
                __stcs(op + tid + 2 * NT, v2);
            }

            __syncthreads();   // everyone done reading stage s

            if (tid == 0 && k + STAGES < count) {
                long long nt = (long long)bid + (long long)(k + STAGES) * grid;
                mbar_expect_tx(bar0 + s * 8, TILE_BYTES);
                bulk_ld(smem_u32 + (uint32_t)(s * TILE_BYTES),
                        base + nt * TILE_F, TILE_BYTES, bar0 + s * 8);
            }

            if (++s == STAGES) { s = 0; p ^= 1; }
        }
    }
}

extern "C" void kernel_launch(void* const* d_in, const int* in_sizes, int n_in,
                              void* d_out, int out_size)
{
    const float* base = (const float*)d_in[0];  // [1, B, 768]
    const float* Wp   = (const float*)d_in[1];
    const float* bp   = (const float*)d_in[2];
    const float* Ws   = (const float*)d_in[3];
    const float* bs   = (const float*)d_in[4];
    float* out = (float*)d_out;

    const int B = in_sizes[0] / 768;
    const int nTiles = B / T_ROWS;

    int grid = nTiles < MAXGRID ? (nTiles > 0 ? nTiles : 1) : MAXGRID;

    static int configured = 0;
    if (!configured) {
        cudaFuncSetAttribute(minireft_v10,
                             cudaFuncAttributeMaxDynamicSharedMemorySize, SM_BYTES);
        configured = 1;
    }

    minireft_v10<<<grid, NT, SM_BYTES>>>(base, out, Wp, bp, Ws, bs, B, nTiles, grid);
}